// round 6
// baseline (speedup 1.0000x reference)
#include <cuda_runtime.h>
#include <math.h>
#include <stdint.h>

#define B_  4
#define S_  2048
#define D_  1024
#define H_  16
#define DH_ 64

__device__ float g_q[(size_t)B_ * H_ * S_ * DH_];
__device__ float g_k[(size_t)B_ * H_ * S_ * DH_];
__device__ float g_v[(size_t)B_ * H_ * S_ * DH_];
__device__ float g_ctx[(size_t)B_ * S_ * D_];

__device__ __forceinline__ uint32_t f2tf32(float x) {
    uint32_t u;
    asm("cvt.rna.tf32.f32 %0, %1;" : "=r"(u) : "f"(x));
    return u;
}
__device__ __forceinline__ float tf32r(float x) { return __uint_as_float(f2tf32(x)); }

__device__ __forceinline__ void mma_tf32(float c[4], uint32_t a0, uint32_t a1,
                                         uint32_t a2, uint32_t a3,
                                         uint32_t b0, uint32_t b1) {
    asm volatile(
        "mma.sync.aligned.m16n8k8.row.col.f32.tf32.tf32.f32 "
        "{%0,%1,%2,%3},{%4,%5,%6,%7},{%8,%9},{%0,%1,%2,%3};"
        : "+f"(c[0]), "+f"(c[1]), "+f"(c[2]), "+f"(c[3])
        : "r"(a0), "r"(a1), "r"(a2), "r"(a3), "r"(b0), "r"(b1));
}

// ---------------------------------------------------------------------------
// TF32 GEMM tile: C[128,256] += A[128,K] * W[256,K]^T, K=1024.
// 256 threads / 8 warps; warp tile 64x64 (acc 128 regs). Double-buffered
// smem [k][m]/[k][n], strides 132/260. BK=16, register prefetch.
// ---------------------------------------------------------------------------
#define AS_W 132
#define BS_W 260
#define AS_SZ (16 * AS_W)
#define BS_SZ (16 * BS_W)

__device__ __forceinline__ void gemm_tf32_128x256(const float* __restrict__ A,
                                                  const float* __restrict__ W,
                                                  float acc[4][8][4])
{
    extern __shared__ uint32_t smg[];
    uint32_t* As = smg;                   // [2][16][132]
    uint32_t* Bs = smg + 2 * AS_SZ;       // [2][16][260]

    const int tid  = threadIdx.x;
    const int lane = tid & 31;
    const int w    = tid >> 5;
    const int wm   = (w & 1) * 64;
    const int wn   = (w >> 1) * 64;
    const int g    = lane >> 2;
    const int tg   = lane & 3;

    const int lr = tid >> 2;          // 0..63
    const int lc = (tid & 3) << 2;    // 0,4,8,12

    const float* Ap = A + (size_t)lr * D_ + lc;
    const float* Wp = W + (size_t)lr * D_ + lc;

#pragma unroll
    for (int mt = 0; mt < 4; ++mt)
#pragma unroll
        for (int nt = 0; nt < 8; ++nt)
#pragma unroll
            for (int c = 0; c < 4; ++c) acc[mt][nt][c] = 0.0f;

    float4 av0 = *(const float4*)(Ap);
    float4 av1 = *(const float4*)(Ap + (size_t)64 * D_);
    float4 bv0 = *(const float4*)(Wp);
    float4 bv1 = *(const float4*)(Wp + (size_t)64 * D_);
    float4 bv2 = *(const float4*)(Wp + (size_t)128 * D_);
    float4 bv3 = *(const float4*)(Wp + (size_t)192 * D_);

    int cur = 0;
#pragma unroll 1
    for (int kt = 0; kt < D_ / 16; ++kt) {
        uint32_t* Ac = As + cur * AS_SZ;
        uint32_t* Bc = Bs + cur * BS_SZ;
        const float* fa0 = (const float*)&av0;
        const float* fa1 = (const float*)&av1;
        const float* fb0 = (const float*)&bv0;
        const float* fb1 = (const float*)&bv1;
        const float* fb2 = (const float*)&bv2;
        const float* fb3 = (const float*)&bv3;
#pragma unroll
        for (int i = 0; i < 4; ++i) {
            Ac[(lc + i) * AS_W + lr]       = f2tf32(fa0[i]);
            Ac[(lc + i) * AS_W + lr + 64]  = f2tf32(fa1[i]);
            Bc[(lc + i) * BS_W + lr]       = f2tf32(fb0[i]);
            Bc[(lc + i) * BS_W + lr + 64]  = f2tf32(fb1[i]);
            Bc[(lc + i) * BS_W + lr + 128] = f2tf32(fb2[i]);
            Bc[(lc + i) * BS_W + lr + 192] = f2tf32(fb3[i]);
        }
        __syncthreads();

        if (kt < D_ / 16 - 1) {
            const int ko = (kt + 1) * 16;
            av0 = *(const float4*)(Ap + ko);
            av1 = *(const float4*)(Ap + ko + (size_t)64 * D_);
            bv0 = *(const float4*)(Wp + ko);
            bv1 = *(const float4*)(Wp + ko + (size_t)64 * D_);
            bv2 = *(const float4*)(Wp + ko + (size_t)128 * D_);
            bv3 = *(const float4*)(Wp + ko + (size_t)192 * D_);
        }

#pragma unroll
        for (int ks = 0; ks < 2; ++ks) {
            const int k0 = ks * 8;
            uint32_t bf[8][2];
#pragma unroll
            for (int nt = 0; nt < 8; ++nt) {
                const int n = wn + nt * 8 + g;
                bf[nt][0] = Bc[(k0 + tg) * BS_W + n];
                bf[nt][1] = Bc[(k0 + tg + 4) * BS_W + n];
            }
#pragma unroll
            for (int mt = 0; mt < 4; ++mt) {
                const int m = wm + mt * 16 + g;
                const uint32_t a0 = Ac[(k0 + tg) * AS_W + m];
                const uint32_t a1 = Ac[(k0 + tg) * AS_W + m + 8];
                const uint32_t a2 = Ac[(k0 + tg + 4) * AS_W + m];
                const uint32_t a3 = Ac[(k0 + tg + 4) * AS_W + m + 8];
#pragma unroll
                for (int nt = 0; nt < 8; ++nt)
                    mma_tf32(acc[mt][nt], a0, a1, a2, a3, bf[nt][0], bf[nt][1]);
            }
        }
        cur ^= 1;
        __syncthreads();
    }
}

// ---------------------------------------------------------------------------
// Fused QKV projection + RoPE + tf32 pre-round epilogue. grid: (4, 64, 3)
// ---------------------------------------------------------------------------
__global__ void __launch_bounds__(256, 1) qkv_gemm_kernel(const float* __restrict__ X,
                                                          const float* __restrict__ Wq,
                                                          const float* __restrict__ Wk,
                                                          const float* __restrict__ Wv,
                                                          const int* __restrict__ pos)
{
    __shared__ float s_inv[32];
    if (threadIdx.x < 32)
        s_inv[threadIdx.x] = powf(10000.0f, -((float)(threadIdx.x * 2)) / 64.0f);

    const int m0 = blockIdx.y << 7;
    const int n0 = blockIdx.x << 8;
    const float* W = (blockIdx.z == 0) ? Wq : ((blockIdx.z == 1) ? Wk : Wv);
    float* out    = (blockIdx.z == 0) ? g_q : ((blockIdx.z == 1) ? g_k : g_v);
    const bool doRope = (blockIdx.z < 2);

    float acc[4][8][4];
    gemm_tf32_128x256(X + (size_t)m0 * D_, W + (size_t)n0 * D_, acc);

    const int lane = threadIdx.x & 31;
    const int w    = threadIdx.x >> 5;
    const int wm   = (w & 1) * 64;
    const int wn   = (w >> 1) * 64;
    const int g    = lane >> 2;
    const int tg   = lane & 3;

#pragma unroll
    for (int mt = 0; mt < 4; ++mt) {
#pragma unroll
        for (int half = 0; half < 2; ++half) {
            const int m = m0 + wm + mt * 16 + g + half * 8;
            const int b = m >> 11;
            const int s = m & (S_ - 1);
            const float fpos = doRope ? (float)pos[b * S_ + s] : 0.0f;
#pragma unroll
            for (int nt = 0; nt < 8; ++nt) {
                const int n  = n0 + wn + nt * 8 + tg * 2;
                const int h  = n >> 6;
                const int dh = n & 63;
                float2 v;
                v.x = acc[mt][nt][half * 2 + 0];
                v.y = acc[mt][nt][half * 2 + 1];
                if (doRope) {
                    const float ang = fpos * s_inv[dh >> 1];
                    float sn, cs;
                    sincosf(ang, &sn, &cs);
                    const float rx = v.x * cs - v.y * sn;
                    const float ry = v.x * sn + v.y * cs;
                    v.x = rx; v.y = ry;
                }
                // pre-round to tf32 so attention staging is a raw bit copy
                v.x = tf32r(v.x);
                v.y = tf32r(v.y);
                *(float2*)&out[((((size_t)b * H_ + h) * S_ + s) << 6) + dh] = v;
            }
        }
    }
}

// ---------------------------------------------------------------------------
// Output projection. grid: (4, 64)
// ---------------------------------------------------------------------------
__global__ void __launch_bounds__(256, 1) oproj_gemm_kernel(const float* __restrict__ Wo,
                                                            float* __restrict__ Out)
{
    const int m0 = blockIdx.y << 7;
    const int n0 = blockIdx.x << 8;

    float acc[4][8][4];
    gemm_tf32_128x256(g_ctx + (size_t)m0 * D_, Wo + (size_t)n0 * D_, acc);

    const int lane = threadIdx.x & 31;
    const int w    = threadIdx.x >> 5;
    const int wm   = (w & 1) * 64;
    const int wn   = (w >> 1) * 64;
    const int g    = lane >> 2;
    const int tg   = lane & 3;

#pragma unroll
    for (int mt = 0; mt < 4; ++mt) {
#pragma unroll
        for (int nt = 0; nt < 8; ++nt) {
            const int n = n0 + wn + nt * 8 + tg * 2;
#pragma unroll
            for (int half = 0; half < 2; ++half) {
                const int m = m0 + wm + mt * 16 + g + half * 8;
                float2 v;
                v.x = acc[mt][nt][half * 2 + 0];
                v.y = acc[mt][nt][half * 2 + 1];
                *(float2*)&Out[(size_t)m * D_ + n] = v;
            }
        }
    }
}

// ---------------------------------------------------------------------------
// Flash attention (causal, tf32 mma): 128 q-rows/CTA, 8 warps, warp owns 16
// rows x 64 cols. q/k/v arrive pre-rounded to tf32 (raw bit staging).
// Vt uses XOR swizzle (i ^ ((d>>3)&3)) -> conflict-free stores AND loads.
// ---------------------------------------------------------------------------
__global__ void __launch_bounds__(256) attn_kernel()
{
    extern __shared__ uint32_t smu[];
    uint32_t* Qs = smu;               // [128][68]
    uint32_t* Ks = Qs + 128 * 68;     // [64][68]
    uint32_t* Vt = Ks + 64 * 68;      // [64][68] transposed w/ swizzle
    uint32_t* Ps = Vt + 64 * 68;      // [128][68]

    const int bh = blockIdx.y;
    const int qt = gridDim.x - 1 - blockIdx.x;
    const int q0 = qt << 7;

    const float* Qg = g_q + ((size_t)bh * S_ << 6);
    const float* Kg = g_k + ((size_t)bh * S_ << 6);
    const float* Vg = g_v + ((size_t)bh * S_ << 6);

    const int tid  = threadIdx.x;
    const int lane = tid & 31;
    const int w    = tid >> 5;
    const int g    = lane >> 2;
    const int tg   = lane & 3;
    const int rw   = w << 4;
    const int r0   = rw + g;
    const int r1   = rw + g + 8;

#pragma unroll
    for (int r = 0; r < 32; ++r) {
        const int e = tid + (r << 8);
        const int i = e >> 6, d = e & 63;
        Qs[i * 68 + d] = __float_as_uint(Qg[((size_t)(q0 + i) << 6) + d] * 0.125f);
    }

    float o[8][4];
#pragma unroll
    for (int nt = 0; nt < 8; ++nt)
#pragma unroll
        for (int c = 0; c < 4; ++c) o[nt][c] = 0.0f;
    float m0r = -1e30f, m1r = -1e30f, l0r = 0.0f, l1r = 0.0f;

    const int nkt = 2 * qt + 2;
#pragma unroll 1
    for (int kt = 0; kt < nkt; ++kt) {
        const int k0 = kt << 6;

        __syncthreads();
#pragma unroll
        for (int r = 0; r < 16; ++r) {
            const int e = tid + (r << 8);
            const int i = e >> 6, d = e & 63;
            Ks[i * 68 + d] = __float_as_uint(Kg[((size_t)(k0 + i) << 6) + d]);
            Vt[d * 68 + (i ^ ((d >> 3) & 3))] = __float_as_uint(Vg[((size_t)(k0 + i) << 6) + d]);
        }
        __syncthreads();

        float acc[8][4];
#pragma unroll
        for (int nt = 0; nt < 8; ++nt)
#pragma unroll
            for (int c = 0; c < 4; ++c) acc[nt][c] = 0.0f;

#pragma unroll
        for (int ks = 0; ks < 8; ++ks) {
            const int d0 = ks * 8;
            const uint32_t a0 = Qs[r0 * 68 + d0 + tg];
            const uint32_t a1 = Qs[r1 * 68 + d0 + tg];
            const uint32_t a2 = Qs[r0 * 68 + d0 + tg + 4];
            const uint32_t a3 = Qs[r1 * 68 + d0 + tg + 4];
#pragma unroll
            for (int nt = 0; nt < 8; ++nt) {
                const uint32_t b0 = Ks[(nt * 8 + g) * 68 + d0 + tg];
                const uint32_t b1 = Ks[(nt * 8 + g) * 68 + d0 + tg + 4];
                mma_tf32(acc[nt], a0, a1, a2, a3, b0, b1);
            }
        }

        if (kt >= 2 * qt) {
            const int row0 = q0 + r0;
            const int row1 = q0 + r1;
#pragma unroll
            for (int nt = 0; nt < 8; ++nt) {
#pragma unroll
                for (int cc = 0; cc < 2; ++cc) {
                    const int col = k0 + nt * 8 + tg * 2 + cc;
                    if (col > row0) acc[nt][cc]     = -1e30f;
                    if (col > row1) acc[nt][cc + 2] = -1e30f;
                }
            }
        }

        float mx0 = -1e30f, mx1 = -1e30f;
#pragma unroll
        for (int nt = 0; nt < 8; ++nt) {
            mx0 = fmaxf(mx0, fmaxf(acc[nt][0], acc[nt][1]));
            mx1 = fmaxf(mx1, fmaxf(acc[nt][2], acc[nt][3]));
        }
        mx0 = fmaxf(mx0, __shfl_xor_sync(0xffffffffu, mx0, 1));
        mx0 = fmaxf(mx0, __shfl_xor_sync(0xffffffffu, mx0, 2));
        mx1 = fmaxf(mx1, __shfl_xor_sync(0xffffffffu, mx1, 1));
        mx1 = fmaxf(mx1, __shfl_xor_sync(0xffffffffu, mx1, 2));

        const float mn0 = fmaxf(m0r, mx0);
        const float mn1 = fmaxf(m1r, mx1);
        const float sc0 = __expf(m0r - mn0);
        const float sc1 = __expf(m1r - mn1);

        float rs0 = 0.0f, rs1 = 0.0f;
#pragma unroll
        for (int nt = 0; nt < 8; ++nt) {
            const float p00 = __expf(acc[nt][0] - mn0);
            const float p01 = __expf(acc[nt][1] - mn0);
            const float p10 = __expf(acc[nt][2] - mn1);
            const float p11 = __expf(acc[nt][3] - mn1);
            rs0 += p00 + p01;
            rs1 += p10 + p11;
            const int cb = nt * 8 + tg * 2;
            Ps[r0 * 68 + cb]     = f2tf32(p00);
            Ps[r0 * 68 + cb + 1] = f2tf32(p01);
            Ps[r1 * 68 + cb]     = f2tf32(p10);
            Ps[r1 * 68 + cb + 1] = f2tf32(p11);
        }
        rs0 += __shfl_xor_sync(0xffffffffu, rs0, 1);
        rs0 += __shfl_xor_sync(0xffffffffu, rs0, 2);
        rs1 += __shfl_xor_sync(0xffffffffu, rs1, 1);
        rs1 += __shfl_xor_sync(0xffffffffu, rs1, 2);

        l0r = l0r * sc0 + rs0;
        l1r = l1r * sc1 + rs1;
        m0r = mn0;
        m1r = mn1;

#pragma unroll
        for (int nt = 0; nt < 8; ++nt) {
            o[nt][0] *= sc0; o[nt][1] *= sc0;
            o[nt][2] *= sc1; o[nt][3] *= sc1;
        }

        __syncwarp();

#pragma unroll
        for (int js = 0; js < 8; ++js) {
            const int j0 = js * 8;
            const uint32_t a0 = Ps[r0 * 68 + j0 + tg];
            const uint32_t a1 = Ps[r1 * 68 + j0 + tg];
            const uint32_t a2 = Ps[r0 * 68 + j0 + tg + 4];
            const uint32_t a3 = Ps[r1 * 68 + j0 + tg + 4];
#pragma unroll
            for (int nt = 0; nt < 8; ++nt) {
                const int vcol = (j0 + tg) ^ (nt & 3);
                const uint32_t b0 = Vt[(nt * 8 + g) * 68 + vcol];
                const uint32_t b1 = Vt[(nt * 8 + g) * 68 + vcol + 4];
                mma_tf32(o[nt], a0, a1, a2, a3, b0, b1);
            }
        }
    }

    const int b = bh >> 4;
    const int h = bh & 15;
    const float invl0 = 1.0f / l0r;
    const float invl1 = 1.0f / l1r;
#pragma unroll
    for (int nt = 0; nt < 8; ++nt) {
        const int col = (h << 6) + nt * 8 + tg * 2;
        float2 v0, v1;
        v0.x = o[nt][0] * invl0; v0.y = o[nt][1] * invl0;
        v1.x = o[nt][2] * invl1; v1.y = o[nt][3] * invl1;
        *(float2*)&g_ctx[((size_t)(b * S_ + q0 + r0)) * D_ + col] = v0;
        *(float2*)&g_ctx[((size_t)(b * S_ + q0 + r1)) * D_ + col] = v1;
    }
}

// ---------------------------------------------------------------------------
// Host launcher
// ---------------------------------------------------------------------------
extern "C" void kernel_launch(void* const* d_in, const int* in_sizes, int n_in,
                              void* d_out, int out_size)
{
    const float* x   = (const float*)d_in[0];
    const int*   pos = (const int*)  d_in[1];
    const float* Wq  = (const float*)d_in[2];
    const float* Wk  = (const float*)d_in[3];
    const float* Wv  = (const float*)d_in[4];
    const float* Wo  = (const float*)d_in[5];
    float* out = (float*)d_out;

    const int PROJ_SMEM = (2 * AS_SZ + 2 * BS_SZ) * sizeof(uint32_t);        // 50176 B
    const int ATTN_SMEM = (128 + 64 + 64 + 128) * 68 * sizeof(uint32_t);      // 104448 B

    cudaFuncSetAttribute(qkv_gemm_kernel,   cudaFuncAttributeMaxDynamicSharedMemorySize, PROJ_SMEM);
    cudaFuncSetAttribute(oproj_gemm_kernel, cudaFuncAttributeMaxDynamicSharedMemorySize, PROJ_SMEM);
    cudaFuncSetAttribute(attn_kernel,       cudaFuncAttributeMaxDynamicSharedMemorySize, ATTN_SMEM);

    qkv_gemm_kernel<<<dim3(D_ / 256, (B_ * S_) / 128, 3), 256, PROJ_SMEM>>>(x, Wq, Wk, Wv, pos);
    attn_kernel<<<dim3(S_ / 128, B_ * H_), 256, ATTN_SMEM>>>();
    oproj_gemm_kernel<<<dim3(D_ / 256, (B_ * S_) / 128), 256, PROJ_SMEM>>>(Wo, out);
}

// round 7
// speedup vs baseline: 1.2133x; 1.2133x over previous
#include <cuda_runtime.h>
#include <math.h>
#include <stdint.h>

#define B_  4
#define S_  2048
#define D_  1024
#define H_  16
#define DH_ 64

__device__ float g_q[(size_t)B_ * H_ * S_ * DH_];
__device__ float g_k[(size_t)B_ * H_ * S_ * DH_];
__device__ float g_v[(size_t)B_ * H_ * S_ * DH_];
__device__ float g_ctx[(size_t)B_ * S_ * D_];
// Pre-rounded (tf32) operands
__device__ float g_xr[(size_t)B_ * S_ * D_];
__device__ float g_wq[(size_t)D_ * D_];
__device__ float g_wk[(size_t)D_ * D_];
__device__ float g_wv[(size_t)D_ * D_];
__device__ float g_wo[(size_t)D_ * D_];

__device__ __forceinline__ uint32_t f2tf32(float x) {
    uint32_t u;
    asm("cvt.rna.tf32.f32 %0, %1;" : "=r"(u) : "f"(x));
    return u;
}
__device__ __forceinline__ float tf32r(float x) { return __uint_as_float(f2tf32(x)); }

__device__ __forceinline__ uint32_t smem_u32(const void* p) {
    uint32_t a;
    asm("{ .reg .u64 t; cvta.to.shared.u64 t, %1; cvt.u32.u64 %0, t; }" : "=r"(a) : "l"(p));
    return a;
}

__device__ __forceinline__ void mma_tf32(float c[4], uint32_t a0, uint32_t a1,
                                         uint32_t a2, uint32_t a3,
                                         uint32_t b0, uint32_t b1) {
    asm volatile(
        "mma.sync.aligned.m16n8k8.row.col.f32.tf32.tf32.f32 "
        "{%0,%1,%2,%3},{%4,%5,%6,%7},{%8,%9},{%0,%1,%2,%3};"
        : "+f"(c[0]), "+f"(c[1]), "+f"(c[2]), "+f"(c[3])
        : "r"(a0), "r"(a1), "r"(a2), "r"(a3), "r"(b0), "r"(b1));
}

__device__ __forceinline__ void cpasync16(uint32_t dst, const void* src) {
    asm volatile("cp.async.ca.shared.global [%0], [%1], 16;" :: "r"(dst), "l"(src) : "memory");
}
#define CP_COMMIT() asm volatile("cp.async.commit_group;" ::: "memory")
#define CP_WAIT2()  asm volatile("cp.async.wait_group 2;" ::: "memory")

// ---------------------------------------------------------------------------
// Pre-round kernel: tf32-round x and all four weight matrices (float4 grid).
// grid: (8192, 5), 256 threads.
// ---------------------------------------------------------------------------
__global__ void __launch_bounds__(256) preround_kernel(const float* __restrict__ x,
                                                       const float* __restrict__ wq,
                                                       const float* __restrict__ wk,
                                                       const float* __restrict__ wv,
                                                       const float* __restrict__ wo)
{
    const int i = blockIdx.x * 256 + threadIdx.x;
    const float* src; float* dst; int n;
    switch (blockIdx.y) {
        case 0:  src = x;  dst = g_xr; n = (B_ * S_ * D_) / 4; break;
        case 1:  src = wq; dst = g_wq; n = (D_ * D_) / 4; break;
        case 2:  src = wk; dst = g_wk; n = (D_ * D_) / 4; break;
        case 3:  src = wv; dst = g_wv; n = (D_ * D_) / 4; break;
        default: src = wo; dst = g_wo; n = (D_ * D_) / 4; break;
    }
    if (i < n) {
        float4 v = ((const float4*)src)[i];
        v.x = tf32r(v.x); v.y = tf32r(v.y); v.z = tf32r(v.z); v.w = tf32r(v.w);
        ((float4*)dst)[i] = v;
    }
}

// ---------------------------------------------------------------------------
// TF32 GEMM tile with cp.async 4-stage pipeline, pre-rounded inputs.
// C[128,128] = A[128,1024] * W[128,1024]^T. 8 warps, warp tile 64x32.
// smem [m][k] pad-20 (bank (20g+tg)%32 all distinct -> conflict-free frags).
// ---------------------------------------------------------------------------
#define PBK    16
#define PPAD   20
#define PSTG_F (128 * PPAD)       // floats per operand per stage
#define PNK    (D_ / PBK)         // 64 chunks

__device__ __forceinline__ void gemm_cp(const float* __restrict__ A,
                                        const float* __restrict__ W,
                                        float acc[4][4][4])
{
    extern __shared__ uint32_t smg[];
    uint32_t* Asm = smg;                    // [4][PSTG_F]
    uint32_t* Bsm = smg + 4 * PSTG_F;       // [4][PSTG_F]

    const int tid  = threadIdx.x;
    const int lane = tid & 31;
    const int w    = tid >> 5;
    const int wm   = (w & 1) * 64;
    const int wn   = (w >> 1) * 32;
    const int g    = lane >> 2;
    const int tg   = lane & 3;

    // Loader: 512 16B-lines per operand per stage; thread handles 2 (A) + 2 (B).
    const int L0 = tid, L1 = tid + 256;
    const int am0 = L0 >> 2, ac0 = (L0 & 3) << 2;
    const int am1 = L1 >> 2, ac1 = (L1 & 3) << 2;

    const uint32_t sA = smem_u32(Asm);
    const uint32_t sB = smem_u32(Bsm);
    const uint32_t dA0 = (uint32_t)(am0 * PPAD + ac0) * 4u;
    const uint32_t dA1 = (uint32_t)(am1 * PPAD + ac1) * 4u;

#pragma unroll
    for (int mt = 0; mt < 4; ++mt)
#pragma unroll
        for (int nt = 0; nt < 4; ++nt)
#pragma unroll
            for (int c = 0; c < 4; ++c) acc[mt][nt][c] = 0.0f;

    // Prologue: stages 0..2
#pragma unroll
    for (int s = 0; s < 3; ++s) {
        const uint32_t bb = (uint32_t)(s * PSTG_F) * 4u;
        const int ko = s * PBK;
        cpasync16(sA + bb + dA0, A + (size_t)am0 * D_ + ko + ac0);
        cpasync16(sA + bb + dA1, A + (size_t)am1 * D_ + ko + ac1);
        cpasync16(sB + bb + dA0, W + (size_t)am0 * D_ + ko + ac0);
        cpasync16(sB + bb + dA1, W + (size_t)am1 * D_ + ko + ac1);
        CP_COMMIT();
    }

#pragma unroll 1
    for (int kc = 0; kc < PNK; ++kc) {
        const int buf = kc & 3;
        CP_WAIT2();
        __syncthreads();

        const uint32_t* Ab = Asm + buf * PSTG_F;
        const uint32_t* Bb = Bsm + buf * PSTG_F;

#pragma unroll
        for (int ks = 0; ks < 2; ++ks) {
            const int k0 = ks * 8;
            uint32_t bf[4][2];
#pragma unroll
            for (int nt = 0; nt < 4; ++nt) {
                const int n = wn + nt * 8 + g;
                bf[nt][0] = Bb[n * PPAD + k0 + tg];
                bf[nt][1] = Bb[n * PPAD + k0 + tg + 4];
            }
#pragma unroll
            for (int mt = 0; mt < 4; ++mt) {
                const int m = wm + mt * 16 + g;
                const uint32_t a0 = Ab[m * PPAD + k0 + tg];
                const uint32_t a1 = Ab[(m + 8) * PPAD + k0 + tg];
                const uint32_t a2 = Ab[m * PPAD + k0 + tg + 4];
                const uint32_t a3 = Ab[(m + 8) * PPAD + k0 + tg + 4];
#pragma unroll
                for (int nt = 0; nt < 4; ++nt)
                    mma_tf32(acc[mt][nt], a0, a1, a2, a3, bf[nt][0], bf[nt][1]);
            }
        }

        if (kc + 3 < PNK) {
            const uint32_t bb = (uint32_t)(((kc + 3) & 3) * PSTG_F) * 4u;
            const int ko = (kc + 3) * PBK;
            cpasync16(sA + bb + dA0, A + (size_t)am0 * D_ + ko + ac0);
            cpasync16(sA + bb + dA1, A + (size_t)am1 * D_ + ko + ac1);
            cpasync16(sB + bb + dA0, W + (size_t)am0 * D_ + ko + ac0);
            cpasync16(sB + bb + dA1, W + (size_t)am1 * D_ + ko + ac1);
            CP_COMMIT();
        }
    }
}

// ---------------------------------------------------------------------------
// Fused QKV projection + RoPE + tf32 pre-round epilogue. grid: (8, 64, 3)
// ---------------------------------------------------------------------------
__global__ void __launch_bounds__(256, 2) qkv_gemm_kernel(const int* __restrict__ pos)
{
    __shared__ float s_inv[32];
    if (threadIdx.x < 32)
        s_inv[threadIdx.x] = powf(10000.0f, -((float)(threadIdx.x * 2)) / 64.0f);

    const int m0 = blockIdx.y << 7;
    const int n0 = blockIdx.x << 7;
    const float* W = (blockIdx.z == 0) ? g_wq : ((blockIdx.z == 1) ? g_wk : g_wv);
    float* out    = (blockIdx.z == 0) ? g_q : ((blockIdx.z == 1) ? g_k : g_v);
    const bool doRope = (blockIdx.z < 2);

    float acc[4][4][4];
    gemm_cp(g_xr + (size_t)m0 * D_, W + (size_t)n0 * D_, acc);

    const int lane = threadIdx.x & 31;
    const int w    = threadIdx.x >> 5;
    const int wm   = (w & 1) * 64;
    const int wn   = (w >> 1) * 32;
    const int g    = lane >> 2;
    const int tg   = lane & 3;

#pragma unroll
    for (int mt = 0; mt < 4; ++mt) {
#pragma unroll
        for (int half = 0; half < 2; ++half) {
            const int m = m0 + wm + mt * 16 + g + half * 8;
            const int b = m >> 11;
            const int s = m & (S_ - 1);
            const float fpos = doRope ? (float)pos[b * S_ + s] : 0.0f;
#pragma unroll
            for (int nt = 0; nt < 4; ++nt) {
                const int n  = n0 + wn + nt * 8 + tg * 2;
                const int h  = n >> 6;
                const int dh = n & 63;
                float2 v;
                v.x = acc[mt][nt][half * 2 + 0];
                v.y = acc[mt][nt][half * 2 + 1];
                if (doRope) {
                    const float ang = fpos * s_inv[dh >> 1];
                    float sn, cs;
                    sincosf(ang, &sn, &cs);
                    const float rx = v.x * cs - v.y * sn;
                    const float ry = v.x * sn + v.y * cs;
                    v.x = rx; v.y = ry;
                }
                v.x = tf32r(v.x);   // attention stages raw bits
                v.y = tf32r(v.y);
                *(float2*)&out[((((size_t)b * H_ + h) * S_ + s) << 6) + dh] = v;
            }
        }
    }
}

// ---------------------------------------------------------------------------
// Output projection. grid: (8, 64). g_ctx is pre-rounded by attention.
// ---------------------------------------------------------------------------
__global__ void __launch_bounds__(256, 2) oproj_gemm_kernel(float* __restrict__ Out)
{
    const int m0 = blockIdx.y << 7;
    const int n0 = blockIdx.x << 7;

    float acc[4][4][4];
    gemm_cp(g_ctx + (size_t)m0 * D_, g_wo + (size_t)n0 * D_, acc);

    const int lane = threadIdx.x & 31;
    const int w    = threadIdx.x >> 5;
    const int wm   = (w & 1) * 64;
    const int wn   = (w >> 1) * 32;
    const int g    = lane >> 2;
    const int tg   = lane & 3;

#pragma unroll
    for (int mt = 0; mt < 4; ++mt) {
#pragma unroll
        for (int nt = 0; nt < 4; ++nt) {
            const int n = n0 + wn + nt * 8 + tg * 2;
#pragma unroll
            for (int half = 0; half < 2; ++half) {
                const int m = m0 + wm + mt * 16 + g + half * 8;
                float2 v;
                v.x = acc[mt][nt][half * 2 + 0];
                v.y = acc[mt][nt][half * 2 + 1];
                *(float2*)&Out[(size_t)m * D_ + n] = v;
            }
        }
    }
}

// ---------------------------------------------------------------------------
// Flash attention (causal, tf32 mma): 128 q-rows/CTA, 8 warps, warp owns 16
// rows x 64 cols. q/k/v pre-rounded to tf32 (raw bit staging).
// Vt XOR swizzle -> conflict-free stores AND loads. Register online softmax.
// ---------------------------------------------------------------------------
__global__ void __launch_bounds__(256) attn_kernel()
{
    extern __shared__ uint32_t smu[];
    uint32_t* Qs = smu;               // [128][68]
    uint32_t* Ks = Qs + 128 * 68;     // [64][68]
    uint32_t* Vt = Ks + 64 * 68;      // [64][68] transposed, swizzled
    uint32_t* Ps = Vt + 64 * 68;      // [128][68]

    const int bh = blockIdx.y;
    const int qt = gridDim.x - 1 - blockIdx.x;
    const int q0 = qt << 7;

    const float* Qg = g_q + ((size_t)bh * S_ << 6);
    const float* Kg = g_k + ((size_t)bh * S_ << 6);
    const float* Vg = g_v + ((size_t)bh * S_ << 6);

    const int tid  = threadIdx.x;
    const int lane = tid & 31;
    const int w    = tid >> 5;
    const int g    = lane >> 2;
    const int tg   = lane & 3;
    const int rw   = w << 4;
    const int r0   = rw + g;
    const int r1   = rw + g + 8;

#pragma unroll
    for (int r = 0; r < 32; ++r) {
        const int e = tid + (r << 8);
        const int i = e >> 6, d = e & 63;
        Qs[i * 68 + d] = __float_as_uint(Qg[((size_t)(q0 + i) << 6) + d] * 0.125f);
    }

    float o[8][4];
#pragma unroll
    for (int nt = 0; nt < 8; ++nt)
#pragma unroll
        for (int c = 0; c < 4; ++c) o[nt][c] = 0.0f;
    float m0r = -1e30f, m1r = -1e30f, l0r = 0.0f, l1r = 0.0f;

    const int nkt = 2 * qt + 2;
#pragma unroll 1
    for (int kt = 0; kt < nkt; ++kt) {
        const int k0 = kt << 6;

        __syncthreads();
#pragma unroll
        for (int r = 0; r < 16; ++r) {
            const int e = tid + (r << 8);
            const int i = e >> 6, d = e & 63;
            Ks[i * 68 + d] = __float_as_uint(Kg[((size_t)(k0 + i) << 6) + d]);
            Vt[d * 68 + (i ^ ((d >> 3) & 3))] = __float_as_uint(Vg[((size_t)(k0 + i) << 6) + d]);
        }
        __syncthreads();

        float acc[8][4];
#pragma unroll
        for (int nt = 0; nt < 8; ++nt)
#pragma unroll
            for (int c = 0; c < 4; ++c) acc[nt][c] = 0.0f;

#pragma unroll
        for (int ks = 0; ks < 8; ++ks) {
            const int d0 = ks * 8;
            const uint32_t a0 = Qs[r0 * 68 + d0 + tg];
            const uint32_t a1 = Qs[r1 * 68 + d0 + tg];
            const uint32_t a2 = Qs[r0 * 68 + d0 + tg + 4];
            const uint32_t a3 = Qs[r1 * 68 + d0 + tg + 4];
#pragma unroll
            for (int nt = 0; nt < 8; ++nt) {
                const uint32_t b0 = Ks[(nt * 8 + g) * 68 + d0 + tg];
                const uint32_t b1 = Ks[(nt * 8 + g) * 68 + d0 + tg + 4];
                mma_tf32(acc[nt], a0, a1, a2, a3, b0, b1);
            }
        }

        if (kt >= 2 * qt) {
            const int row0 = q0 + r0;
            const int row1 = q0 + r1;
#pragma unroll
            for (int nt = 0; nt < 8; ++nt) {
#pragma unroll
                for (int cc = 0; cc < 2; ++cc) {
                    const int col = k0 + nt * 8 + tg * 2 + cc;
                    if (col > row0) acc[nt][cc]     = -1e30f;
                    if (col > row1) acc[nt][cc + 2] = -1e30f;
                }
            }
        }

        float mx0 = -1e30f, mx1 = -1e30f;
#pragma unroll
        for (int nt = 0; nt < 8; ++nt) {
            mx0 = fmaxf(mx0, fmaxf(acc[nt][0], acc[nt][1]));
            mx1 = fmaxf(mx1, fmaxf(acc[nt][2], acc[nt][3]));
        }
        mx0 = fmaxf(mx0, __shfl_xor_sync(0xffffffffu, mx0, 1));
        mx0 = fmaxf(mx0, __shfl_xor_sync(0xffffffffu, mx0, 2));
        mx1 = fmaxf(mx1, __shfl_xor_sync(0xffffffffu, mx1, 1));
        mx1 = fmaxf(mx1, __shfl_xor_sync(0xffffffffu, mx1, 2));

        const float mn0 = fmaxf(m0r, mx0);
        const float mn1 = fmaxf(m1r, mx1);
        const float sc0 = __expf(m0r - mn0);
        const float sc1 = __expf(m1r - mn1);

        float rs0 = 0.0f, rs1 = 0.0f;
#pragma unroll
        for (int nt = 0; nt < 8; ++nt) {
            const float p00 = __expf(acc[nt][0] - mn0);
            const float p01 = __expf(acc[nt][1] - mn0);
            const float p10 = __expf(acc[nt][2] - mn1);
            const float p11 = __expf(acc[nt][3] - mn1);
            rs0 += p00 + p01;
            rs1 += p10 + p11;
            const int cb = nt * 8 + tg * 2;
            Ps[r0 * 68 + cb]     = f2tf32(p00);
            Ps[r0 * 68 + cb + 1] = f2tf32(p01);
            Ps[r1 * 68 + cb]     = f2tf32(p10);
            Ps[r1 * 68 + cb + 1] = f2tf32(p11);
        }
        rs0 += __shfl_xor_sync(0xffffffffu, rs0, 1);
        rs0 += __shfl_xor_sync(0xffffffffu, rs0, 2);
        rs1 += __shfl_xor_sync(0xffffffffu, rs1, 1);
        rs1 += __shfl_xor_sync(0xffffffffu, rs1, 2);

        l0r = l0r * sc0 + rs0;
        l1r = l1r * sc1 + rs1;
        m0r = mn0;
        m1r = mn1;

#pragma unroll
        for (int nt = 0; nt < 8; ++nt) {
            o[nt][0] *= sc0; o[nt][1] *= sc0;
            o[nt][2] *= sc1; o[nt][3] *= sc1;
        }

        __syncwarp();

#pragma unroll
        for (int js = 0; js < 8; ++js) {
            const int j0 = js * 8;
            const uint32_t a0 = Ps[r0 * 68 + j0 + tg];
            const uint32_t a1 = Ps[r1 * 68 + j0 + tg];
            const uint32_t a2 = Ps[r0 * 68 + j0 + tg + 4];
            const uint32_t a3 = Ps[r1 * 68 + j0 + tg + 4];
#pragma unroll
            for (int nt = 0; nt < 8; ++nt) {
                const int vcol = (j0 + tg) ^ (nt & 3);
                const uint32_t b0 = Vt[(nt * 8 + g) * 68 + vcol];
                const uint32_t b1 = Vt[(nt * 8 + g) * 68 + vcol + 4];
                mma_tf32(o[nt], a0, a1, a2, a3, b0, b1);
            }
        }
    }

    const int b = bh >> 4;
    const int h = bh & 15;
    const float invl0 = 1.0f / l0r;
    const float invl1 = 1.0f / l1r;
#pragma unroll
    for (int nt = 0; nt < 8; ++nt) {
        const int col = (h << 6) + nt * 8 + tg * 2;
        float2 v0, v1;
        v0.x = tf32r(o[nt][0] * invl0); v0.y = tf32r(o[nt][1] * invl0);
        v1.x = tf32r(o[nt][2] * invl1); v1.y = tf32r(o[nt][3] * invl1);
        *(float2*)&g_ctx[((size_t)(b * S_ + q0 + r0)) * D_ + col] = v0;
        *(float2*)&g_ctx[((size_t)(b * S_ + q0 + r1)) * D_ + col] = v1;
    }
}

// ---------------------------------------------------------------------------
// Host launcher
// ---------------------------------------------------------------------------
extern "C" void kernel_launch(void* const* d_in, const int* in_sizes, int n_in,
                              void* d_out, int out_size)
{
    const float* x   = (const float*)d_in[0];
    const int*   pos = (const int*)  d_in[1];
    const float* Wq  = (const float*)d_in[2];
    const float* Wk  = (const float*)d_in[3];
    const float* Wv  = (const float*)d_in[4];
    const float* Wo  = (const float*)d_in[5];
    float* out = (float*)d_out;

    const int PROJ_SMEM = 8 * PSTG_F * sizeof(uint32_t);                  // 81920 B
    const int ATTN_SMEM = (128 + 64 + 64 + 128) * 68 * sizeof(uint32_t);  // 104448 B

    cudaFuncSetAttribute(qkv_gemm_kernel,   cudaFuncAttributeMaxDynamicSharedMemorySize, PROJ_SMEM);
    cudaFuncSetAttribute(oproj_gemm_kernel, cudaFuncAttributeMaxDynamicSharedMemorySize, PROJ_SMEM);
    cudaFuncSetAttribute(attn_kernel,       cudaFuncAttributeMaxDynamicSharedMemorySize, ATTN_SMEM);

    preround_kernel<<<dim3(8192, 5), 256>>>(x, Wq, Wk, Wv, Wo);
    qkv_gemm_kernel<<<dim3(D_ / 128, (B_ * S_) / 128, 3), 256, PROJ_SMEM>>>(pos);
    attn_kernel<<<dim3(S_ / 128, B_ * H_), 256, ATTN_SMEM>>>();
    oproj_gemm_kernel<<<dim3(D_ / 128, (B_ * S_) / 128), 256, PROJ_SMEM>>>(out);
}

// round 8
// speedup vs baseline: 1.2846x; 1.0588x over previous
#include <cuda_runtime.h>
#include <math.h>
#include <stdint.h>

#define B_  4
#define S_  2048
#define D_  1024
#define H_  16
#define DH_ 64

__device__ float g_q[(size_t)B_ * H_ * S_ * DH_];
__device__ float g_k[(size_t)B_ * H_ * S_ * DH_];
__device__ float g_v[(size_t)B_ * H_ * S_ * DH_];
__device__ float g_ctx[(size_t)B_ * S_ * D_];
// Pre-rounded (tf32) operands
__device__ float g_xr[(size_t)B_ * S_ * D_];
__device__ float g_wq[(size_t)D_ * D_];
__device__ float g_wk[(size_t)D_ * D_];
__device__ float g_wv[(size_t)D_ * D_];
__device__ float g_wo[(size_t)D_ * D_];

__device__ __forceinline__ uint32_t f2tf32(float x) {
    uint32_t u;
    asm("cvt.rna.tf32.f32 %0, %1;" : "=r"(u) : "f"(x));
    return u;
}
__device__ __forceinline__ float tf32r(float x) { return __uint_as_float(f2tf32(x)); }

__device__ __forceinline__ uint32_t smem_u32(const void* p) {
    uint32_t a;
    asm("{ .reg .u64 t; cvta.to.shared.u64 t, %1; cvt.u32.u64 %0, t; }" : "=r"(a) : "l"(p));
    return a;
}

__device__ __forceinline__ void mma_tf32(float c[4], uint32_t a0, uint32_t a1,
                                         uint32_t a2, uint32_t a3,
                                         uint32_t b0, uint32_t b1) {
    asm volatile(
        "mma.sync.aligned.m16n8k8.row.col.f32.tf32.tf32.f32 "
        "{%0,%1,%2,%3},{%4,%5,%6,%7},{%8,%9},{%0,%1,%2,%3};"
        : "+f"(c[0]), "+f"(c[1]), "+f"(c[2]), "+f"(c[3])
        : "r"(a0), "r"(a1), "r"(a2), "r"(a3), "r"(b0), "r"(b1));
}

__device__ __forceinline__ void cpasync16(uint32_t dst, const void* src) {
    asm volatile("cp.async.ca.shared.global [%0], [%1], 16;" :: "r"(dst), "l"(src) : "memory");
}
#define CP_COMMIT() asm volatile("cp.async.commit_group;" ::: "memory")
#define CP_WAIT2()  asm volatile("cp.async.wait_group 2;" ::: "memory")

// ---------------------------------------------------------------------------
// Pre-round kernel: tf32-round x and all four weight matrices.
// ---------------------------------------------------------------------------
__global__ void __launch_bounds__(256) preround_kernel(const float* __restrict__ x,
                                                       const float* __restrict__ wq,
                                                       const float* __restrict__ wk,
                                                       const float* __restrict__ wv,
                                                       const float* __restrict__ wo)
{
    const int i = blockIdx.x * 256 + threadIdx.x;
    const float* src; float* dst; int n;
    switch (blockIdx.y) {
        case 0:  src = x;  dst = g_xr; n = (B_ * S_ * D_) / 4; break;
        case 1:  src = wq; dst = g_wq; n = (D_ * D_) / 4; break;
        case 2:  src = wk; dst = g_wk; n = (D_ * D_) / 4; break;
        case 3:  src = wv; dst = g_wv; n = (D_ * D_) / 4; break;
        default: src = wo; dst = g_wo; n = (D_ * D_) / 4; break;
    }
    if (i < n) {
        float4 v = ((const float4*)src)[i];
        v.x = tf32r(v.x); v.y = tf32r(v.y); v.z = tf32r(v.z); v.w = tf32r(v.w);
        ((float4*)dst)[i] = v;
    }
}

// ---------------------------------------------------------------------------
// TF32 GEMM tile with cp.async 4-stage pipeline (unchanged from R7).
// ---------------------------------------------------------------------------
#define PBK    16
#define PPAD   20
#define PSTG_F (128 * PPAD)
#define PNK    (D_ / PBK)

__device__ __forceinline__ void gemm_cp(const float* __restrict__ A,
                                        const float* __restrict__ W,
                                        float acc[4][4][4])
{
    extern __shared__ uint32_t smg[];
    uint32_t* Asm = smg;
    uint32_t* Bsm = smg + 4 * PSTG_F;

    const int tid  = threadIdx.x;
    const int lane = tid & 31;
    const int w    = tid >> 5;
    const int wm   = (w & 1) * 64;
    const int wn   = (w >> 1) * 32;
    const int g    = lane >> 2;
    const int tg   = lane & 3;

    const int L0 = tid, L1 = tid + 256;
    const int am0 = L0 >> 2, ac0 = (L0 & 3) << 2;
    const int am1 = L1 >> 2, ac1 = (L1 & 3) << 2;

    const uint32_t sA = smem_u32(Asm);
    const uint32_t sB = smem_u32(Bsm);
    const uint32_t dA0 = (uint32_t)(am0 * PPAD + ac0) * 4u;
    const uint32_t dA1 = (uint32_t)(am1 * PPAD + ac1) * 4u;

#pragma unroll
    for (int mt = 0; mt < 4; ++mt)
#pragma unroll
        for (int nt = 0; nt < 4; ++nt)
#pragma unroll
            for (int c = 0; c < 4; ++c) acc[mt][nt][c] = 0.0f;

#pragma unroll
    for (int s = 0; s < 3; ++s) {
        const uint32_t bb = (uint32_t)(s * PSTG_F) * 4u;
        const int ko = s * PBK;
        cpasync16(sA + bb + dA0, A + (size_t)am0 * D_ + ko + ac0);
        cpasync16(sA + bb + dA1, A + (size_t)am1 * D_ + ko + ac1);
        cpasync16(sB + bb + dA0, W + (size_t)am0 * D_ + ko + ac0);
        cpasync16(sB + bb + dA1, W + (size_t)am1 * D_ + ko + ac1);
        CP_COMMIT();
    }

#pragma unroll 1
    for (int kc = 0; kc < PNK; ++kc) {
        const int buf = kc & 3;
        CP_WAIT2();
        __syncthreads();

        const uint32_t* Ab = Asm + buf * PSTG_F;
        const uint32_t* Bb = Bsm + buf * PSTG_F;

#pragma unroll
        for (int ks = 0; ks < 2; ++ks) {
            const int k0 = ks * 8;
            uint32_t bf[4][2];
#pragma unroll
            for (int nt = 0; nt < 4; ++nt) {
                const int n = wn + nt * 8 + g;
                bf[nt][0] = Bb[n * PPAD + k0 + tg];
                bf[nt][1] = Bb[n * PPAD + k0 + tg + 4];
            }
#pragma unroll
            for (int mt = 0; mt < 4; ++mt) {
                const int m = wm + mt * 16 + g;
                const uint32_t a0 = Ab[m * PPAD + k0 + tg];
                const uint32_t a1 = Ab[(m + 8) * PPAD + k0 + tg];
                const uint32_t a2 = Ab[m * PPAD + k0 + tg + 4];
                const uint32_t a3 = Ab[(m + 8) * PPAD + k0 + tg + 4];
#pragma unroll
                for (int nt = 0; nt < 4; ++nt)
                    mma_tf32(acc[mt][nt], a0, a1, a2, a3, bf[nt][0], bf[nt][1]);
            }
        }

        if (kc + 3 < PNK) {
            const uint32_t bb = (uint32_t)(((kc + 3) & 3) * PSTG_F) * 4u;
            const int ko = (kc + 3) * PBK;
            cpasync16(sA + bb + dA0, A + (size_t)am0 * D_ + ko + ac0);
            cpasync16(sA + bb + dA1, A + (size_t)am1 * D_ + ko + ac1);
            cpasync16(sB + bb + dA0, W + (size_t)am0 * D_ + ko + ac0);
            cpasync16(sB + bb + dA1, W + (size_t)am1 * D_ + ko + ac1);
            CP_COMMIT();
        }
    }
}

// ---------------------------------------------------------------------------
// Fused QKV projection + RoPE + tf32 pre-round epilogue. grid: (8, 64, 3)
// ---------------------------------------------------------------------------
__global__ void __launch_bounds__(256, 2) qkv_gemm_kernel(const int* __restrict__ pos)
{
    __shared__ float s_inv[32];
    if (threadIdx.x < 32)
        s_inv[threadIdx.x] = powf(10000.0f, -((float)(threadIdx.x * 2)) / 64.0f);

    const int m0 = blockIdx.y << 7;
    const int n0 = blockIdx.x << 7;
    const float* W = (blockIdx.z == 0) ? g_wq : ((blockIdx.z == 1) ? g_wk : g_wv);
    float* out    = (blockIdx.z == 0) ? g_q : ((blockIdx.z == 1) ? g_k : g_v);
    const bool doRope = (blockIdx.z < 2);

    float acc[4][4][4];
    gemm_cp(g_xr + (size_t)m0 * D_, W + (size_t)n0 * D_, acc);

    const int lane = threadIdx.x & 31;
    const int w    = threadIdx.x >> 5;
    const int wm   = (w & 1) * 64;
    const int wn   = (w >> 1) * 32;
    const int g    = lane >> 2;
    const int tg   = lane & 3;

#pragma unroll
    for (int mt = 0; mt < 4; ++mt) {
#pragma unroll
        for (int half = 0; half < 2; ++half) {
            const int m = m0 + wm + mt * 16 + g + half * 8;
            const int b = m >> 11;
            const int s = m & (S_ - 1);
            const float fpos = doRope ? (float)pos[b * S_ + s] : 0.0f;
#pragma unroll
            for (int nt = 0; nt < 4; ++nt) {
                const int n  = n0 + wn + nt * 8 + tg * 2;
                const int h  = n >> 6;
                const int dh = n & 63;
                float2 v;
                v.x = acc[mt][nt][half * 2 + 0];
                v.y = acc[mt][nt][half * 2 + 1];
                if (doRope) {
                    const float ang = fpos * s_inv[dh >> 1];
                    float sn, cs;
                    sincosf(ang, &sn, &cs);
                    const float rx = v.x * cs - v.y * sn;
                    const float ry = v.x * sn + v.y * cs;
                    v.x = rx; v.y = ry;
                }
                v.x = tf32r(v.x);
                v.y = tf32r(v.y);
                *(float2*)&out[((((size_t)b * H_ + h) * S_ + s) << 6) + dh] = v;
            }
        }
    }
}

// ---------------------------------------------------------------------------
// Output projection. grid: (8, 64).
// ---------------------------------------------------------------------------
__global__ void __launch_bounds__(256, 2) oproj_gemm_kernel(float* __restrict__ Out)
{
    const int m0 = blockIdx.y << 7;
    const int n0 = blockIdx.x << 7;

    float acc[4][4][4];
    gemm_cp(g_ctx + (size_t)m0 * D_, g_wo + (size_t)n0 * D_, acc);

    const int lane = threadIdx.x & 31;
    const int w    = threadIdx.x >> 5;
    const int wm   = (w & 1) * 64;
    const int wn   = (w >> 1) * 32;
    const int g    = lane >> 2;
    const int tg   = lane & 3;

#pragma unroll
    for (int mt = 0; mt < 4; ++mt) {
#pragma unroll
        for (int nt = 0; nt < 4; ++nt) {
            const int n = n0 + wn + nt * 8 + tg * 2;
#pragma unroll
            for (int half = 0; half < 2; ++half) {
                const int m = m0 + wm + mt * 16 + g + half * 8;
                float2 v;
                v.x = acc[mt][nt][half * 2 + 0];
                v.y = acc[mt][nt][half * 2 + 1];
                *(float2*)&Out[(size_t)m * D_ + n] = v;
            }
        }
    }
}

// ---------------------------------------------------------------------------
// Flash attention v3 (causal, tf32 mma):
//  - CTA = 128 q-rows, 4 warps (128 threads); warp w owns rows [32w, 32w+32)
//    as 2 m-tiles x 8 n-tiles -> B-fragments amortized 2x (1.5 LDS/mma).
//  - Register online softmax (quad shfl), P stored as uint2 (STS.64).
//  - 2 CTAs/SM (regs ~170, smem 104448*2 < 228K) -> 8 warps/SM.
// ---------------------------------------------------------------------------
__global__ void __launch_bounds__(128, 2) attn_kernel()
{
    extern __shared__ uint32_t smu[];
    uint32_t* Qs = smu;               // [128][68]
    uint32_t* Ks = Qs + 128 * 68;     // [64][68]
    uint32_t* Vt = Ks + 64 * 68;      // [64][68] transposed, XOR-swizzled
    uint32_t* Ps = Vt + 64 * 68;      // [128][68]

    const int bh = blockIdx.y;
    const int qt = gridDim.x - 1 - blockIdx.x;
    const int q0 = qt << 7;

    const float* Qg = g_q + ((size_t)bh * S_ << 6);
    const float* Kg = g_k + ((size_t)bh * S_ << 6);
    const float* Vg = g_v + ((size_t)bh * S_ << 6);

    const int tid  = threadIdx.x;
    const int lane = tid & 31;
    const int w    = tid >> 5;
    const int g    = lane >> 2;
    const int tg   = lane & 3;
    const int rw   = w << 5;                       // warp row origin (32 rows)

    // Q tile (scaled; already tf32-rounded in projection epilogue)
#pragma unroll
    for (int r = 0; r < 64; ++r) {
        const int e = tid + (r << 7);
        const int i = e >> 6, d = e & 63;
        Qs[i * 68 + d] = __float_as_uint(Qg[((size_t)(q0 + i) << 6) + d] * 0.125f);
    }

    float o[2][8][4];
#pragma unroll
    for (int mt = 0; mt < 2; ++mt)
#pragma unroll
        for (int nt = 0; nt < 8; ++nt)
#pragma unroll
            for (int c = 0; c < 4; ++c) o[mt][nt][c] = 0.0f;
    float mrow[2][2], lrow[2][2];
#pragma unroll
    for (int mt = 0; mt < 2; ++mt) {
        mrow[mt][0] = -1e30f; mrow[mt][1] = -1e30f;
        lrow[mt][0] = 0.0f;   lrow[mt][1] = 0.0f;
    }

    const int nkt = 2 * qt + 2;
#pragma unroll 1
    for (int kt = 0; kt < nkt; ++kt) {
        const int k0 = kt << 6;

        __syncthreads();
#pragma unroll
        for (int r = 0; r < 32; ++r) {
            const int e = tid + (r << 7);
            const int i = e >> 6, d = e & 63;
            Ks[i * 68 + d] = __float_as_uint(Kg[((size_t)(k0 + i) << 6) + d]);
            Vt[d * 68 + (i ^ ((d >> 3) & 3))] = __float_as_uint(Vg[((size_t)(k0 + i) << 6) + d]);
        }
        __syncthreads();

        // Scores: 2 m-tiles x 8 n-tiles
        float acc[2][8][4];
#pragma unroll
        for (int mt = 0; mt < 2; ++mt)
#pragma unroll
            for (int nt = 0; nt < 8; ++nt)
#pragma unroll
                for (int c = 0; c < 4; ++c) acc[mt][nt][c] = 0.0f;

#pragma unroll
        for (int ks = 0; ks < 8; ++ks) {
            const int d0 = ks * 8;
            uint32_t af[2][4];
#pragma unroll
            for (int mt = 0; mt < 2; ++mt) {
                const int rA = rw + (mt << 4) + g;
                af[mt][0] = Qs[rA * 68 + d0 + tg];
                af[mt][1] = Qs[(rA + 8) * 68 + d0 + tg];
                af[mt][2] = Qs[rA * 68 + d0 + tg + 4];
                af[mt][3] = Qs[(rA + 8) * 68 + d0 + tg + 4];
            }
#pragma unroll
            for (int nt = 0; nt < 8; ++nt) {
                const uint32_t b0 = Ks[(nt * 8 + g) * 68 + d0 + tg];
                const uint32_t b1 = Ks[(nt * 8 + g) * 68 + d0 + tg + 4];
#pragma unroll
                for (int mt = 0; mt < 2; ++mt)
                    mma_tf32(acc[mt][nt], af[mt][0], af[mt][1], af[mt][2], af[mt][3], b0, b1);
            }
        }

        // Causal mask
        if (kt >= 2 * qt) {
#pragma unroll
            for (int mt = 0; mt < 2; ++mt) {
                const int row0 = q0 + rw + (mt << 4) + g;
                const int row1 = row0 + 8;
#pragma unroll
                for (int nt = 0; nt < 8; ++nt) {
#pragma unroll
                    for (int cc = 0; cc < 2; ++cc) {
                        const int col = k0 + nt * 8 + tg * 2 + cc;
                        if (col > row0) acc[mt][nt][cc]     = -1e30f;
                        if (col > row1) acc[mt][nt][cc + 2] = -1e30f;
                    }
                }
            }
        }

        // Register online softmax per m-tile (quad shfl over tg lanes)
#pragma unroll
        for (int mt = 0; mt < 2; ++mt) {
            const int rA = rw + (mt << 4) + g;
            const int rB = rA + 8;
            float mx0 = -1e30f, mx1 = -1e30f;
#pragma unroll
            for (int nt = 0; nt < 8; ++nt) {
                mx0 = fmaxf(mx0, fmaxf(acc[mt][nt][0], acc[mt][nt][1]));
                mx1 = fmaxf(mx1, fmaxf(acc[mt][nt][2], acc[mt][nt][3]));
            }
            mx0 = fmaxf(mx0, __shfl_xor_sync(0xffffffffu, mx0, 1));
            mx0 = fmaxf(mx0, __shfl_xor_sync(0xffffffffu, mx0, 2));
            mx1 = fmaxf(mx1, __shfl_xor_sync(0xffffffffu, mx1, 1));
            mx1 = fmaxf(mx1, __shfl_xor_sync(0xffffffffu, mx1, 2));

            const float mn0 = fmaxf(mrow[mt][0], mx0);
            const float mn1 = fmaxf(mrow[mt][1], mx1);
            const float sc0 = __expf(mrow[mt][0] - mn0);
            const float sc1 = __expf(mrow[mt][1] - mn1);

            float rs0 = 0.0f, rs1 = 0.0f;
#pragma unroll
            for (int nt = 0; nt < 8; ++nt) {
                const float p00 = __expf(acc[mt][nt][0] - mn0);
                const float p01 = __expf(acc[mt][nt][1] - mn0);
                const float p10 = __expf(acc[mt][nt][2] - mn1);
                const float p11 = __expf(acc[mt][nt][3] - mn1);
                rs0 += p00 + p01;
                rs1 += p10 + p11;
                const int cb = nt * 8 + tg * 2;
                uint2 pA, pB;
                pA.x = f2tf32(p00); pA.y = f2tf32(p01);
                pB.x = f2tf32(p10); pB.y = f2tf32(p11);
                *(uint2*)&Ps[rA * 68 + cb] = pA;
                *(uint2*)&Ps[rB * 68 + cb] = pB;
            }
            rs0 += __shfl_xor_sync(0xffffffffu, rs0, 1);
            rs0 += __shfl_xor_sync(0xffffffffu, rs0, 2);
            rs1 += __shfl_xor_sync(0xffffffffu, rs1, 1);
            rs1 += __shfl_xor_sync(0xffffffffu, rs1, 2);

            lrow[mt][0] = lrow[mt][0] * sc0 + rs0;
            lrow[mt][1] = lrow[mt][1] * sc1 + rs1;
            mrow[mt][0] = mn0;
            mrow[mt][1] = mn1;

#pragma unroll
            for (int nt = 0; nt < 8; ++nt) {
                o[mt][nt][0] *= sc0; o[mt][nt][1] *= sc0;
                o[mt][nt][2] *= sc1; o[mt][nt][3] *= sc1;
            }
        }

        __syncwarp();

        // PV
#pragma unroll
        for (int js = 0; js < 8; ++js) {
            const int j0 = js * 8;
            uint32_t af[2][4];
#pragma unroll
            for (int mt = 0; mt < 2; ++mt) {
                const int rA = rw + (mt << 4) + g;
                af[mt][0] = Ps[rA * 68 + j0 + tg];
                af[mt][1] = Ps[(rA + 8) * 68 + j0 + tg];
                af[mt][2] = Ps[rA * 68 + j0 + tg + 4];
                af[mt][3] = Ps[(rA + 8) * 68 + j0 + tg + 4];
            }
#pragma unroll
            for (int nt = 0; nt < 8; ++nt) {
                const int vcol = (j0 + tg) ^ (nt & 3);
                const uint32_t b0 = Vt[(nt * 8 + g) * 68 + vcol];
                const uint32_t b1 = Vt[(nt * 8 + g) * 68 + vcol + 4];
#pragma unroll
                for (int mt = 0; mt < 2; ++mt)
                    mma_tf32(o[mt][nt], af[mt][0], af[mt][1], af[mt][2], af[mt][3], b0, b1);
            }
        }
    }

    // Epilogue -> ctx (pre-rounded for oproj)
    const int b = bh >> 4;
    const int h = bh & 15;
#pragma unroll
    for (int mt = 0; mt < 2; ++mt) {
        const int rA = rw + (mt << 4) + g;
        const int rB = rA + 8;
        const float invl0 = 1.0f / lrow[mt][0];
        const float invl1 = 1.0f / lrow[mt][1];
#pragma unroll
        for (int nt = 0; nt < 8; ++nt) {
            const int col = (h << 6) + nt * 8 + tg * 2;
            float2 v0, v1;
            v0.x = tf32r(o[mt][nt][0] * invl0); v0.y = tf32r(o[mt][nt][1] * invl0);
            v1.x = tf32r(o[mt][nt][2] * invl1); v1.y = tf32r(o[mt][nt][3] * invl1);
            *(float2*)&g_ctx[((size_t)(b * S_ + q0 + rA)) * D_ + col] = v0;
            *(float2*)&g_ctx[((size_t)(b * S_ + q0 + rB)) * D_ + col] = v1;
        }
    }
}

// ---------------------------------------------------------------------------
// Host launcher
// ---------------------------------------------------------------------------
extern "C" void kernel_launch(void* const* d_in, const int* in_sizes, int n_in,
                              void* d_out, int out_size)
{
    const float* x   = (const float*)d_in[0];
    const int*   pos = (const int*)  d_in[1];
    const float* Wq  = (const float*)d_in[2];
    const float* Wk  = (const float*)d_in[3];
    const float* Wv  = (const float*)d_in[4];
    const float* Wo  = (const float*)d_in[5];
    float* out = (float*)d_out;

    const int PROJ_SMEM = 8 * PSTG_F * sizeof(uint32_t);                  // 81920 B
    const int ATTN_SMEM = (128 + 64 + 64 + 128) * 68 * sizeof(uint32_t);  // 104448 B

    cudaFuncSetAttribute(qkv_gemm_kernel,   cudaFuncAttributeMaxDynamicSharedMemorySize, PROJ_SMEM);
    cudaFuncSetAttribute(oproj_gemm_kernel, cudaFuncAttributeMaxDynamicSharedMemorySize, PROJ_SMEM);
    cudaFuncSetAttribute(attn_kernel,       cudaFuncAttributeMaxDynamicSharedMemorySize, ATTN_SMEM);

    preround_kernel<<<dim3(8192, 5), 256>>>(x, Wq, Wk, Wv, Wo);
    qkv_gemm_kernel<<<dim3(D_ / 128, (B_ * S_) / 128, 3), 256, PROJ_SMEM>>>(pos);
    attn_kernel<<<dim3(S_ / 128, B_ * H_), 128, ATTN_SMEM>>>();
    oproj_gemm_kernel<<<dim3(D_ / 128, (B_ * S_) / 128), 256, PROJ_SMEM>>>(out);
}

// round 9
// speedup vs baseline: 1.5677x; 1.2204x over previous
#include <cuda_runtime.h>
#include <math.h>
#include <stdint.h>

#define B_  4
#define S_  2048
#define D_  1024
#define H_  16
#define DH_ 64

__device__ float g_q[(size_t)B_ * H_ * S_ * DH_];
__device__ float g_k[(size_t)B_ * H_ * S_ * DH_];
__device__ float g_v[(size_t)B_ * H_ * S_ * DH_];
__device__ float g_ctx[(size_t)B_ * S_ * D_];
// Pre-rounded (tf32) operands
__device__ float g_xr[(size_t)B_ * S_ * D_];
__device__ float g_wq[(size_t)D_ * D_];
__device__ float g_wk[(size_t)D_ * D_];
__device__ float g_wv[(size_t)D_ * D_];
__device__ float g_wo[(size_t)D_ * D_];

__device__ __forceinline__ uint32_t f2tf32(float x) {
    uint32_t u;
    asm("cvt.rna.tf32.f32 %0, %1;" : "=r"(u) : "f"(x));
    return u;
}
__device__ __forceinline__ float tf32r(float x) { return __uint_as_float(f2tf32(x)); }

__device__ __forceinline__ float ex2(float x) {
    float r;
    asm("ex2.approx.f32 %0, %1;" : "=f"(r) : "f"(x));
    return r;
}

__device__ __forceinline__ uint32_t smem_u32(const void* p) {
    uint32_t a;
    asm("{ .reg .u64 t; cvta.to.shared.u64 t, %1; cvt.u32.u64 %0, t; }" : "=r"(a) : "l"(p));
    return a;
}

__device__ __forceinline__ void mma_tf32(float c[4], uint32_t a0, uint32_t a1,
                                         uint32_t a2, uint32_t a3,
                                         uint32_t b0, uint32_t b1) {
    asm volatile(
        "mma.sync.aligned.m16n8k8.row.col.f32.tf32.tf32.f32 "
        "{%0,%1,%2,%3},{%4,%5,%6,%7},{%8,%9},{%0,%1,%2,%3};"
        : "+f"(c[0]), "+f"(c[1]), "+f"(c[2]), "+f"(c[3])
        : "r"(a0), "r"(a1), "r"(a2), "r"(a3), "r"(b0), "r"(b1));
}

__device__ __forceinline__ void cpasync16(uint32_t dst, const void* src) {
    asm volatile("cp.async.ca.shared.global [%0], [%1], 16;" :: "r"(dst), "l"(src) : "memory");
}
#define CP_COMMIT() asm volatile("cp.async.commit_group;" ::: "memory")
#define CP_WAIT0()  asm volatile("cp.async.wait_group 0;" ::: "memory")
#define CP_WAIT1()  asm volatile("cp.async.wait_group 1;" ::: "memory")

// ---------------------------------------------------------------------------
// Pre-round kernel: tf32-round x and all four weight matrices.
// ---------------------------------------------------------------------------
__global__ void __launch_bounds__(256) preround_kernel(const float* __restrict__ x,
                                                       const float* __restrict__ wq,
                                                       const float* __restrict__ wk,
                                                       const float* __restrict__ wv,
                                                       const float* __restrict__ wo)
{
    const int i = blockIdx.x * 256 + threadIdx.x;
    const float* src; float* dst; int n;
    switch (blockIdx.y) {
        case 0:  src = x;  dst = g_xr; n = (B_ * S_ * D_) / 4; break;
        case 1:  src = wq; dst = g_wq; n = (D_ * D_) / 4; break;
        case 2:  src = wk; dst = g_wk; n = (D_ * D_) / 4; break;
        case 3:  src = wv; dst = g_wv; n = (D_ * D_) / 4; break;
        default: src = wo; dst = g_wo; n = (D_ * D_) / 4; break;
    }
    if (i < n) {
        float4 v = ((const float4*)src)[i];
        v.x = tf32r(v.x); v.y = tf32r(v.y); v.z = tf32r(v.z); v.w = tf32r(v.w);
        ((float4*)dst)[i] = v;
    }
}

// ---------------------------------------------------------------------------
// TF32 GEMM: C[128,128] = A[128,1024] * W[128,1024]^T.
// BK=32, 3-stage cp.async pipeline, exact-depth waits (race-free tail).
// smem [m][k] pad-36 -> fragment LDS bank (4g+tg)%32 all distinct.
// ---------------------------------------------------------------------------
#define PBK    32
#define PPAD   36
#define PSTG_F (128 * PPAD)        // floats per operand per stage (4608)
#define PNK    (D_ / PBK)          // 32 chunks

__device__ __forceinline__ void gemm_cp(const float* __restrict__ A,
                                        const float* __restrict__ W,
                                        float acc[4][4][4])
{
    extern __shared__ uint32_t smg[];
    uint32_t* Asm = smg;                    // [3][PSTG_F]
    uint32_t* Bsm = smg + 3 * PSTG_F;       // [3][PSTG_F]

    const int tid  = threadIdx.x;
    const int lane = tid & 31;
    const int w    = tid >> 5;
    const int wm   = (w & 1) * 64;
    const int wn   = (w >> 1) * 32;
    const int g    = lane >> 2;
    const int tg   = lane & 3;

    const uint32_t sA = smem_u32(Asm);
    const uint32_t sB = smem_u32(Bsm);

    // Loader: 1024 16B-lines per operand per stage; 4 per thread per operand.
    int lrow[4], lcol[4];
    uint32_t ldst[4];
#pragma unroll
    for (int i = 0; i < 4; ++i) {
        const int L = tid + 256 * i;
        lrow[i] = L >> 3;
        lcol[i] = (L & 7) << 2;
        ldst[i] = (uint32_t)(lrow[i] * PPAD + lcol[i]) * 4u;
    }

#pragma unroll
    for (int mt = 0; mt < 4; ++mt)
#pragma unroll
        for (int nt = 0; nt < 4; ++nt)
#pragma unroll
            for (int c = 0; c < 4; ++c) acc[mt][nt][c] = 0.0f;

    // Prologue: stages 0..1
#pragma unroll
    for (int s = 0; s < 2; ++s) {
        const uint32_t bb = (uint32_t)(s * PSTG_F) * 4u;
        const int ko = s * PBK;
#pragma unroll
        for (int i = 0; i < 4; ++i) {
            cpasync16(sA + bb + ldst[i], A + (size_t)lrow[i] * D_ + ko + lcol[i]);
            cpasync16(sB + bb + ldst[i], W + (size_t)lrow[i] * D_ + ko + lcol[i]);
        }
        CP_COMMIT();
    }

#pragma unroll 1
    for (int kc = 0; kc < PNK; ++kc) {
        // Exact depth: 1 newer group outstanding except on the last chunk.
        if (kc < PNK - 1) CP_WAIT1(); else CP_WAIT0();
        __syncthreads();

        const int buf = kc - (kc / 3) * 3;   // kc % 3
        const uint32_t* Ab = Asm + buf * PSTG_F;
        const uint32_t* Bb = Bsm + buf * PSTG_F;

#pragma unroll
        for (int ks = 0; ks < 4; ++ks) {
            const int k0 = ks * 8;
            uint32_t bf[4][2];
#pragma unroll
            for (int nt = 0; nt < 4; ++nt) {
                const int n = wn + nt * 8 + g;
                bf[nt][0] = Bb[n * PPAD + k0 + tg];
                bf[nt][1] = Bb[n * PPAD + k0 + tg + 4];
            }
#pragma unroll
            for (int mt = 0; mt < 4; ++mt) {
                const int m = wm + mt * 16 + g;
                const uint32_t a0 = Ab[m * PPAD + k0 + tg];
                const uint32_t a1 = Ab[(m + 8) * PPAD + k0 + tg];
                const uint32_t a2 = Ab[m * PPAD + k0 + tg + 4];
                const uint32_t a3 = Ab[(m + 8) * PPAD + k0 + tg + 4];
#pragma unroll
                for (int nt = 0; nt < 4; ++nt)
                    mma_tf32(acc[mt][nt], a0, a1, a2, a3, bf[nt][0], bf[nt][1]);
            }
        }

        if (kc + 2 < PNK) {
            const int nb = (kc + 2) - ((kc + 2) / 3) * 3;
            const uint32_t bb = (uint32_t)(nb * PSTG_F) * 4u;
            const int ko = (kc + 2) * PBK;
#pragma unroll
            for (int i = 0; i < 4; ++i) {
                cpasync16(sA + bb + ldst[i], A + (size_t)lrow[i] * D_ + ko + lcol[i]);
                cpasync16(sB + bb + ldst[i], W + (size_t)lrow[i] * D_ + ko + lcol[i]);
            }
            CP_COMMIT();
        }
    }
}

// ---------------------------------------------------------------------------
// Fused QKV projection + RoPE + tf32 pre-round epilogue. grid: (8, 64, 3)
// ---------------------------------------------------------------------------
__global__ void __launch_bounds__(256, 2) qkv_gemm_kernel(const int* __restrict__ pos)
{
    __shared__ float s_inv[32];
    if (threadIdx.x < 32)
        s_inv[threadIdx.x] = powf(10000.0f, -((float)(threadIdx.x * 2)) / 64.0f);

    const int m0 = blockIdx.y << 7;
    const int n0 = blockIdx.x << 7;
    const float* W = (blockIdx.z == 0) ? g_wq : ((blockIdx.z == 1) ? g_wk : g_wv);
    float* out    = (blockIdx.z == 0) ? g_q : ((blockIdx.z == 1) ? g_k : g_v);
    const bool doRope = (blockIdx.z < 2);

    float acc[4][4][4];
    gemm_cp(g_xr + (size_t)m0 * D_, W + (size_t)n0 * D_, acc);

    const int lane = threadIdx.x & 31;
    const int w    = threadIdx.x >> 5;
    const int wm   = (w & 1) * 64;
    const int wn   = (w >> 1) * 32;
    const int g    = lane >> 2;
    const int tg   = lane & 3;

#pragma unroll
    for (int mt = 0; mt < 4; ++mt) {
#pragma unroll
        for (int half = 0; half < 2; ++half) {
            const int m = m0 + wm + mt * 16 + g + half * 8;
            const int b = m >> 11;
            const int s = m & (S_ - 1);
            const float fpos = doRope ? (float)pos[b * S_ + s] : 0.0f;
#pragma unroll
            for (int nt = 0; nt < 4; ++nt) {
                const int n  = n0 + wn + nt * 8 + tg * 2;
                const int h  = n >> 6;
                const int dh = n & 63;
                float2 v;
                v.x = acc[mt][nt][half * 2 + 0];
                v.y = acc[mt][nt][half * 2 + 1];
                if (doRope) {
                    const float ang = fpos * s_inv[dh >> 1];
                    float sn, cs;
                    sincosf(ang, &sn, &cs);
                    const float rx = v.x * cs - v.y * sn;
                    const float ry = v.x * sn + v.y * cs;
                    v.x = rx; v.y = ry;
                }
                v.x = tf32r(v.x);
                v.y = tf32r(v.y);
                *(float2*)&out[((((size_t)b * H_ + h) * S_ + s) << 6) + dh] = v;
            }
        }
    }
}

// ---------------------------------------------------------------------------
// Output projection. grid: (8, 64).
// ---------------------------------------------------------------------------
__global__ void __launch_bounds__(256, 2) oproj_gemm_kernel(float* __restrict__ Out)
{
    const int m0 = blockIdx.y << 7;
    const int n0 = blockIdx.x << 7;

    float acc[4][4][4];
    gemm_cp(g_ctx + (size_t)m0 * D_, g_wo + (size_t)n0 * D_, acc);

    const int lane = threadIdx.x & 31;
    const int w    = threadIdx.x >> 5;
    const int wm   = (w & 1) * 64;
    const int wn   = (w >> 1) * 32;
    const int g    = lane >> 2;
    const int tg   = lane & 3;

#pragma unroll
    for (int mt = 0; mt < 4; ++mt) {
#pragma unroll
        for (int nt = 0; nt < 4; ++nt) {
            const int n = n0 + wn + nt * 8 + tg * 2;
#pragma unroll
            for (int half = 0; half < 2; ++half) {
                const int m = m0 + wm + mt * 16 + g + half * 8;
                float2 v;
                v.x = acc[mt][nt][half * 2 + 0];
                v.y = acc[mt][nt][half * 2 + 1];
                *(float2*)&Out[(size_t)m * D_ + n] = v;
            }
        }
    }
}

// ---------------------------------------------------------------------------
// Flash attention (causal, tf32 mma), 128 q-rows/CTA, 4 warps, warp owns
// 32 rows x 64 cols. Softmax in log2 domain (scale folds 0.125*log2e).
// K staged via cp.async; V transposed manually (XOR swizzle).
// grid: (bh=64, qtiles=16), heaviest q-tiles scheduled first.
// ---------------------------------------------------------------------------
#define QSCALE 0.180336887f   // 0.125 * log2(e)

__global__ void __launch_bounds__(128, 2) attn_kernel()
{
    extern __shared__ uint32_t smu[];
    uint32_t* Qs = smu;               // [128][68]
    uint32_t* Ks = Qs + 128 * 68;     // [64][68]
    uint32_t* Vt = Ks + 64 * 68;      // [64][68] transposed, XOR-swizzled
    uint32_t* Ps = Vt + 64 * 68;      // [128][68]

    const int bh = blockIdx.x;
    const int qt = gridDim.y - 1 - blockIdx.y;   // heavy tiles first
    const int q0 = qt << 7;

    const float* Qg = g_q + ((size_t)bh * S_ << 6);
    const float* Kg = g_k + ((size_t)bh * S_ << 6);
    const float* Vg = g_v + ((size_t)bh * S_ << 6);

    const int tid  = threadIdx.x;
    const int lane = tid & 31;
    const int w    = tid >> 5;
    const int g    = lane >> 2;
    const int tg   = lane & 3;
    const int rw   = w << 5;

    const uint32_t sK = smem_u32(Ks);

    // Q tile: scale into log2 domain, re-round to tf32
#pragma unroll
    for (int r = 0; r < 64; ++r) {
        const int e = tid + (r << 7);
        const int i = e >> 6, d = e & 63;
        Qs[i * 68 + d] = f2tf32(Qg[((size_t)(q0 + i) << 6) + d] * QSCALE);
    }

    float o[2][8][4];
#pragma unroll
    for (int mt = 0; mt < 2; ++mt)
#pragma unroll
        for (int nt = 0; nt < 8; ++nt)
#pragma unroll
            for (int c = 0; c < 4; ++c) o[mt][nt][c] = 0.0f;
    float mrow[2][2], lrow[2][2];
#pragma unroll
    for (int mt = 0; mt < 2; ++mt) {
        mrow[mt][0] = -1e30f; mrow[mt][1] = -1e30f;
        lrow[mt][0] = 0.0f;   lrow[mt][1] = 0.0f;
    }

    const int nkt = 2 * qt + 2;
#pragma unroll 1
    for (int kt = 0; kt < nkt; ++kt) {
        const int k0 = kt << 6;

        __syncthreads();
        // K tile via cp.async (raw copy, 8 lines/thread)
#pragma unroll
        for (int i = 0; i < 8; ++i) {
            const int L = tid + (i << 7);
            const int row = L >> 4;
            const int colf = (L & 15) << 2;
            cpasync16(sK + (uint32_t)(row * 68 + colf) * 4u,
                      Kg + ((size_t)(k0 + row) << 6) + colf);
        }
        CP_COMMIT();
        // V tile transposed (manual, swizzled)
#pragma unroll
        for (int r = 0; r < 32; ++r) {
            const int e = tid + (r << 7);
            const int i = e >> 6, d = e & 63;
            Vt[d * 68 + (i ^ ((d >> 3) & 3))] = __float_as_uint(Vg[((size_t)(k0 + i) << 6) + d]);
        }
        CP_WAIT0();
        __syncthreads();

        // Scores (log2 domain): 2 m-tiles x 8 n-tiles
        float acc[2][8][4];
#pragma unroll
        for (int mt = 0; mt < 2; ++mt)
#pragma unroll
            for (int nt = 0; nt < 8; ++nt)
#pragma unroll
                for (int c = 0; c < 4; ++c) acc[mt][nt][c] = 0.0f;

#pragma unroll
        for (int ks = 0; ks < 8; ++ks) {
            const int d0 = ks * 8;
            uint32_t af[2][4];
#pragma unroll
            for (int mt = 0; mt < 2; ++mt) {
                const int rA = rw + (mt << 4) + g;
                af[mt][0] = Qs[rA * 68 + d0 + tg];
                af[mt][1] = Qs[(rA + 8) * 68 + d0 + tg];
                af[mt][2] = Qs[rA * 68 + d0 + tg + 4];
                af[mt][3] = Qs[(rA + 8) * 68 + d0 + tg + 4];
            }
#pragma unroll
            for (int nt = 0; nt < 8; ++nt) {
                const uint32_t b0 = Ks[(nt * 8 + g) * 68 + d0 + tg];
                const uint32_t b1 = Ks[(nt * 8 + g) * 68 + d0 + tg + 4];
#pragma unroll
                for (int mt = 0; mt < 2; ++mt)
                    mma_tf32(acc[mt][nt], af[mt][0], af[mt][1], af[mt][2], af[mt][3], b0, b1);
            }
        }

        // Causal mask
        if (kt >= 2 * qt) {
#pragma unroll
            for (int mt = 0; mt < 2; ++mt) {
                const int row0 = q0 + rw + (mt << 4) + g;
                const int row1 = row0 + 8;
#pragma unroll
                for (int nt = 0; nt < 8; ++nt) {
#pragma unroll
                    for (int cc = 0; cc < 2; ++cc) {
                        const int col = k0 + nt * 8 + tg * 2 + cc;
                        if (col > row0) acc[mt][nt][cc]     = -1e30f;
                        if (col > row1) acc[mt][nt][cc + 2] = -1e30f;
                    }
                }
            }
        }

        // Register online softmax (log2 domain; quad shfl over tg lanes)
#pragma unroll
        for (int mt = 0; mt < 2; ++mt) {
            const int rA = rw + (mt << 4) + g;
            const int rB = rA + 8;
            float mx0 = -1e30f, mx1 = -1e30f;
#pragma unroll
            for (int nt = 0; nt < 8; ++nt) {
                mx0 = fmaxf(mx0, fmaxf(acc[mt][nt][0], acc[mt][nt][1]));
                mx1 = fmaxf(mx1, fmaxf(acc[mt][nt][2], acc[mt][nt][3]));
            }
            mx0 = fmaxf(mx0, __shfl_xor_sync(0xffffffffu, mx0, 1));
            mx0 = fmaxf(mx0, __shfl_xor_sync(0xffffffffu, mx0, 2));
            mx1 = fmaxf(mx1, __shfl_xor_sync(0xffffffffu, mx1, 1));
            mx1 = fmaxf(mx1, __shfl_xor_sync(0xffffffffu, mx1, 2));

            const float mn0 = fmaxf(mrow[mt][0], mx0);
            const float mn1 = fmaxf(mrow[mt][1], mx1);
            const float sc0 = ex2(mrow[mt][0] - mn0);
            const float sc1 = ex2(mrow[mt][1] - mn1);

            float rs0 = 0.0f, rs1 = 0.0f;
#pragma unroll
            for (int nt = 0; nt < 8; ++nt) {
                const float p00 = ex2(acc[mt][nt][0] - mn0);
                const float p01 = ex2(acc[mt][nt][1] - mn0);
                const float p10 = ex2(acc[mt][nt][2] - mn1);
                const float p11 = ex2(acc[mt][nt][3] - mn1);
                rs0 += p00 + p01;
                rs1 += p10 + p11;
                const int cb = nt * 8 + tg * 2;
                uint2 pA, pB;
                pA.x = f2tf32(p00); pA.y = f2tf32(p01);
                pB.x = f2tf32(p10); pB.y = f2tf32(p11);
                *(uint2*)&Ps[rA * 68 + cb] = pA;
                *(uint2*)&Ps[rB * 68 + cb] = pB;
            }
            rs0 += __shfl_xor_sync(0xffffffffu, rs0, 1);
            rs0 += __shfl_xor_sync(0xffffffffu, rs0, 2);
            rs1 += __shfl_xor_sync(0xffffffffu, rs1, 1);
            rs1 += __shfl_xor_sync(0xffffffffu, rs1, 2);

            lrow[mt][0] = lrow[mt][0] * sc0 + rs0;
            lrow[mt][1] = lrow[mt][1] * sc1 + rs1;
            mrow[mt][0] = mn0;
            mrow[mt][1] = mn1;

#pragma unroll
            for (int nt = 0; nt < 8; ++nt) {
                o[mt][nt][0] *= sc0; o[mt][nt][1] *= sc0;
                o[mt][nt][2] *= sc1; o[mt][nt][3] *= sc1;
            }
        }

        __syncwarp();

        // PV
#pragma unroll
        for (int js = 0; js < 8; ++js) {
            const int j0 = js * 8;
            uint32_t af[2][4];
#pragma unroll
            for (int mt = 0; mt < 2; ++mt) {
                const int rA = rw + (mt << 4) + g;
                af[mt][0] = Ps[rA * 68 + j0 + tg];
                af[mt][1] = Ps[(rA + 8) * 68 + j0 + tg];
                af[mt][2] = Ps[rA * 68 + j0 + tg + 4];
                af[mt][3] = Ps[(rA + 8) * 68 + j0 + tg + 4];
            }
#pragma unroll
            for (int nt = 0; nt < 8; ++nt) {
                const int vcol = (j0 + tg) ^ (nt & 3);
                const uint32_t b0 = Vt[(nt * 8 + g) * 68 + vcol];
                const uint32_t b1 = Vt[(nt * 8 + g) * 68 + vcol + 4];
#pragma unroll
                for (int mt = 0; mt < 2; ++mt)
                    mma_tf32(o[mt][nt], af[mt][0], af[mt][1], af[mt][2], af[mt][3], b0, b1);
            }
        }
    }

    // Epilogue -> ctx (pre-rounded for oproj)
    const int b = bh >> 4;
    const int h = bh & 15;
#pragma unroll
    for (int mt = 0; mt < 2; ++mt) {
        const int rA = rw + (mt << 4) + g;
        const int rB = rA + 8;
        const float invl0 = 1.0f / lrow[mt][0];
        const float invl1 = 1.0f / lrow[mt][1];
#pragma unroll
        for (int nt = 0; nt < 8; ++nt) {
            const int col = (h << 6) + nt * 8 + tg * 2;
            float2 v0, v1;
            v0.x = tf32r(o[mt][nt][0] * invl0); v0.y = tf32r(o[mt][nt][1] * invl0);
            v1.x = tf32r(o[mt][nt][2] * invl1); v1.y = tf32r(o[mt][nt][3] * invl1);
            *(float2*)&g_ctx[((size_t)(b * S_ + q0 + rA)) * D_ + col] = v0;
            *(float2*)&g_ctx[((size_t)(b * S_ + q0 + rB)) * D_ + col] = v1;
        }
    }
}

// ---------------------------------------------------------------------------
// Host launcher
// ---------------------------------------------------------------------------
extern "C" void kernel_launch(void* const* d_in, const int* in_sizes, int n_in,
                              void* d_out, int out_size)
{
    const float* x   = (const float*)d_in[0];
    const int*   pos = (const int*)  d_in[1];
    const float* Wq  = (const float*)d_in[2];
    const float* Wk  = (const float*)d_in[3];
    const float* Wv  = (const float*)d_in[4];
    const float* Wo  = (const float*)d_in[5];
    float* out = (float*)d_out;

    const int PROJ_SMEM = 6 * PSTG_F * sizeof(uint32_t);                  // 110592 B
    const int ATTN_SMEM = (128 + 64 + 64 + 128) * 68 * sizeof(uint32_t);  // 104448 B

    cudaFuncSetAttribute(qkv_gemm_kernel,   cudaFuncAttributeMaxDynamicSharedMemorySize, PROJ_SMEM);
    cudaFuncSetAttribute(oproj_gemm_kernel, cudaFuncAttributeMaxDynamicSharedMemorySize, PROJ_SMEM);
    cudaFuncSetAttribute(attn_kernel,       cudaFuncAttributeMaxDynamicSharedMemorySize, ATTN_SMEM);

    preround_kernel<<<dim3(8192, 5), 256>>>(x, Wq, Wk, Wv, Wo);
    qkv_gemm_kernel<<<dim3(D_ / 128, (B_ * S_) / 128, 3), 256, PROJ_SMEM>>>(pos);
    attn_kernel<<<dim3(B_ * H_, S_ / 128), 128, ATTN_SMEM>>>();
    oproj_gemm_kernel<<<dim3(D_ / 128, (B_ * S_) / 128), 256, PROJ_SMEM>>>(out);
}